// round 9
// baseline (speedup 1.0000x reference)
#include <cuda_runtime.h>
#include <math.h>

#define NP 8192
#define NB 64   // number of 128-wide blocks

__device__ float g_xtT[64 * NP];            // [k][i] transposed embeddings
__device__ float g_sq[NP];
__device__ float g_D[67108864];             // logits matrix, 256 MB

__device__ __forceinline__ unsigned fenc(float f) {
    unsigned u = __float_as_uint(f);
    return (u & 0x80000000u) ? ~u : (u | 0x80000000u);
}
__device__ __forceinline__ float fdec(unsigned k) {
    return (k & 0x80000000u) ? __uint_as_float(k ^ 0x80000000u)
                             : __uint_as_float(~k);
}

// ============================ embed ============================
__global__ void __launch_bounds__(256, 1) k_embed(
        const float* __restrict__ X, const float* __restrict__ W,
        const float* __restrict__ b, float* __restrict__ out) {
    __shared__ float s_acc[256];
    int tid = threadIdx.x;
    int row = (blockIdx.x << 2) + (tid >> 6);
    int col = tid & 63;
    const float* xr = X + (size_t)row * 128;
    float acc = 0.f;
    #pragma unroll 16
    for (int k = 0; k < 128; ++k)
        acc = fmaf(__ldg(xr + k), __ldg(W + k * 64 + col), acc);
    acc = __fadd_rn(acc, __ldg(b + col));
    out[row * 64 + col] = acc;           // X_tilde output
    g_xtT[col * NP + row] = acc;         // transposed copy for GEMM
    s_acc[tid] = acc;
    __syncthreads();
    if (tid < 128) {
        int sub = tid >> 5, lane = tid & 31;
        float a = s_acc[sub * 64 + lane];
        float c = s_acc[sub * 64 + 32 + lane];
        float v = a * a + c * c;
        #pragma unroll
        for (int o = 16; o; o >>= 1) v += __shfl_xor_sync(0xffffffffu, v, o);
        if (!lane) g_sq[(blockIdx.x << 2) + sub] = v;
    }
}

// ============================ gemm -> logits matrix ============================
// smem: sA/sB [k][i] stride 132 (conflict-free: a-frag 16-lane broadcast,
// b-frag 4tj distinct per phase, tile STS 4*i4 distinct). sC: 128x128 with
// XOR swizzle (off ^ ((jl>>2&7)<<2)) -> STS.128 and LDS.128 both conflict-free.
struct GU {
    union {
        struct { float sA[64 * 132]; float sB[64 * 132]; } ab;
        float sC[128 * 128];
    };
    float sqi[128];
    float sqj[128];
};

__global__ void __launch_bounds__(256, 2) k_gemm(const float* __restrict__ tparam) {
    extern __shared__ char smraw[];
    GU& sm = *reinterpret_cast<GU*>(smraw);
    const int tid = threadIdx.x;

    // triangular block decode: bi <= bj
    int bidx = blockIdx.x, bi = 0;
    while (bidx >= NB - bi) { bidx -= NB - bi; ++bi; }
    const int bj = bi + bidx;
    const int I = bi * 128, J = bj * 128;
    const float scale = expf(fminf(fmaxf(tparam[0], -5.f), 5.f));
    const int ti = tid >> 4, tj = tid & 15;

    #pragma unroll
    for (int it = 0; it < 8; ++it) {
        int f = it * 256 + tid;
        int k = f >> 5, i4 = f & 31;
        *(float4*)&sm.ab.sA[k * 132 + i4 * 4] =
            *(const float4*)&g_xtT[k * NP + I + i4 * 4];
        *(float4*)&sm.ab.sB[k * 132 + i4 * 4] =
            *(const float4*)&g_xtT[k * NP + J + i4 * 4];
    }
    if (tid < 128) { sm.sqi[tid] = g_sq[I + tid]; sm.sqj[tid] = g_sq[J + tid]; }
    __syncthreads();

    float acc[8][8];
    #pragma unroll
    for (int u = 0; u < 8; ++u)
        #pragma unroll
        for (int v = 0; v < 8; ++v) acc[u][v] = 0.f;

    #pragma unroll 4
    for (int k = 0; k < 64; ++k) {
        float4 a0 = *(const float4*)&sm.ab.sA[k * 132 + ti * 4];
        float4 a1 = *(const float4*)&sm.ab.sA[k * 132 + 64 + ti * 4];
        float4 b0 = *(const float4*)&sm.ab.sB[k * 132 + tj * 4];
        float4 b1 = *(const float4*)&sm.ab.sB[k * 132 + 64 + tj * 4];
        float av[8] = {a0.x, a0.y, a0.z, a0.w, a1.x, a1.y, a1.z, a1.w};
        float bv[8] = {b0.x, b0.y, b0.z, b0.w, b1.x, b1.y, b1.z, b1.w};
        #pragma unroll
        for (int u = 0; u < 8; ++u)
            #pragma unroll
            for (int v = 0; v < 8; ++v)
                acc[u][v] = fmaf(av[u], bv[v], acc[u][v]);
    }

    // epilogue: logits in-place (exact reference op order)
    float si[8], sj[8];
    #pragma unroll
    for (int u = 0; u < 8; ++u)
        si[u] = sm.sqi[(u < 4) ? ti * 4 + u : 64 + ti * 4 + (u - 4)];
    #pragma unroll
    for (int v = 0; v < 8; ++v)
        sj[v] = sm.sqj[(v < 4) ? tj * 4 + v : 64 + tj * 4 + (v - 4)];
    #pragma unroll
    for (int u = 0; u < 8; ++u)
        #pragma unroll
        for (int v = 0; v < 8; ++v) {
            float d = __fadd_rn(__fadd_rn(si[u], sj[v]),
                                -__fmul_rn(2.0f, acc[u][v]));
            acc[u][v] = __fmul_rn(fmaxf(d, 0.0f), scale);
        }

    // direct store: block (bi rows, bj cols)
    #pragma unroll
    for (int u = 0; u < 8; ++u) {
        int gi = I + ((u < 4) ? ti * 4 + u : 64 + ti * 4 + (u - 4));
        *(float4*)&g_D[(size_t)gi * NP + J + tj * 4] =
            make_float4(acc[u][0], acc[u][1], acc[u][2], acc[u][3]);
        *(float4*)&g_D[(size_t)gi * NP + J + 64 + tj * 4] =
            make_float4(acc[u][4], acc[u][5], acc[u][6], acc[u][7]);
    }

    if (bi != bj) {
        // transposed store via swizzled smem stage (values bit-identical by symmetry)
        __syncthreads();
        #pragma unroll
        for (int v = 0; v < 8; ++v) {
            int jl = (v < 4) ? tj * 4 + v : 64 + tj * 4 + (v - 4);
            int sw = ((jl >> 2) & 7) << 2;
            *(float4*)&sm.sC[jl * 128 + ((ti * 4) ^ sw)] =
                make_float4(acc[0][v], acc[1][v], acc[2][v], acc[3][v]);
            *(float4*)&sm.sC[jl * 128 + (64 + ((ti * 4) ^ sw))] =
                make_float4(acc[4][v], acc[5][v], acc[6][v], acc[7][v]);
        }
        __syncthreads();
        #pragma unroll
        for (int it = 0; it < 16; ++it) {
            int f = it * 256 + tid;
            int jl = f >> 5, i4 = f & 31;
            int sw = ((jl >> 2) & 7) << 2;
            int off = i4 * 4;
            int phys = (off < 64) ? (off ^ sw) : (64 + ((off - 64) ^ sw));
            float4 vv = *(const float4*)&sm.sC[jl * 128 + phys];
            *(float4*)&g_D[(size_t)(J + jl) * NP + I + i4 * 4] = vv;
        }
    }
}

// ============================ select: warp-per-row exact top-16 ============================
__global__ void __launch_bounds__(256) k_select(
        const float* __restrict__ q, float* __restrict__ out) {
    const int lane = threadIdx.x & 31;
    const int gw = blockIdx.x * 8 + (threadIdx.x >> 5);
    const unsigned FULL = 0xffffffffu;

    for (int rr = 0; rr < 4; ++rr) {
        const int row = gw * 4 + rr;
        const float* Drow = g_D + (size_t)row * NP;
        const float* qrow = q + (size_t)row * NP;
        // distributed sorted list: slot `lane` (lanes 0..15 are the answer)
        unsigned kHi = 0xFF800000u, kLo = 0xFFFFFFFFu;  // +inf sentinel
        float lgS = 0.f;
        float th = __int_as_float(0x7f800000);

        for (int m = 0; m < 64; ++m) {
            float4 v = *(const float4*)&Drow[(m * 32 + lane) * 4];
            bool p0 = (v.x - 17.0f) <= th;   // gumbel in [-2.92,16.64] -> exact bound
            bool p1 = (v.y - 17.0f) <= th;
            bool p2 = (v.z - 17.0f) <= th;
            bool p3 = (v.w - 17.0f) <= th;
            unsigned any = __ballot_sync(FULL, p0 | p1 | p2 | p3);
            if (!any) continue;

            float pe0 = 0.f, pe1 = 0.f, pe2 = 0.f, pe3 = 0.f;
            if (p0 | p1 | p2 | p3) {
                float4 qv = *(const float4*)&qrow[(m * 32 + lane) * 4];
                if (p0) pe0 = __fadd_rn(v.x, logf(-logf(qv.x)));
                if (p1) pe1 = __fadd_rn(v.y, logf(-logf(qv.y)));
                if (p2) pe2 = __fadd_rn(v.z, logf(-logf(qv.z)));
                if (p3) pe3 = __fadd_rn(v.w, logf(-logf(qv.w)));
            }
            #pragma unroll
            for (int c = 0; c < 4; ++c) {
                float pc = (c == 0) ? pe0 : (c == 1) ? pe1 : (c == 2) ? pe2 : pe3;
                float vc = (c == 0) ? v.x : (c == 1) ? v.y : (c == 2) ? v.z : v.w;
                bool  pp = (c == 0) ? p0 : (c == 1) ? p1 : (c == 2) ? p2 : p3;
                unsigned mc = __ballot_sync(FULL, pp);
                while (mc) {
                    int L = __ffs(mc) - 1; mc &= mc - 1;
                    float np = __shfl_sync(FULL, pc, L);
                    float nl = __shfl_sync(FULL, vc, L);
                    unsigned nk = fenc(np);
                    unsigned nj = (unsigned)((m * 32 + L) * 4 + c);
                    bool le = (kHi < nk) | ((kHi == nk) & (kLo <= nj));
                    int pos = __popc(__ballot_sync(FULL, le));
                    unsigned sHi = __shfl_up_sync(FULL, kHi, 1);
                    unsigned sLo = __shfl_up_sync(FULL, kLo, 1);
                    float    sLg = __shfl_up_sync(FULL, lgS, 1);
                    if (lane == pos)      { kHi = nk;  kLo = nj;  lgS = nl;  }
                    else if (lane > pos)  { kHi = sHi; kLo = sLo; lgS = sLg; }
                }
            }
            th = fdec(__shfl_sync(FULL, kHi, 15));
        }

        if (lane < 16) {
            out[524288 + row * 16 + lane] = (float)kLo;     // edge_index[0]
            out[655360 + row * 16 + lane] = (float)row;     // edge_index[1]
            out[786432 + row * 16 + lane] = -lgS;           // logprobs
        }
    }
}

extern "C" void kernel_launch(void* const* d_in, const int* in_sizes, int n_in,
                              void* d_out, int out_size) {
    const float* X = (const float*)d_in[0];
    const float* W = (const float*)d_in[1];
    const float* b = (const float*)d_in[2];
    const float* t = (const float*)d_in[3];
    const float* q = (const float*)d_in[4];
    float* out = (float*)d_out;

    k_embed<<<2048, 256>>>(X, W, b, out);
    int smem = (int)sizeof(GU);
    cudaFuncSetAttribute(k_gemm, cudaFuncAttributeMaxDynamicSharedMemorySize, smem);
    k_gemm<<<NB * (NB + 1) / 2, 256, smem>>>(t);
    k_select<<<256, 256>>>(q, out);
}

// round 10
// speedup vs baseline: 1.5766x; 1.5766x over previous
#include <cuda_runtime.h>
#include <math.h>

#define NP 8192
#define NB 64   // number of 128-wide blocks

__device__ float g_xtT[64 * NP];            // [k][i] transposed embeddings
__device__ float g_sq[NP];
__device__ float g_D[67108864];             // logits matrix, 256 MB

__device__ __forceinline__ unsigned fenc(float f) {
    unsigned u = __float_as_uint(f);
    return (u & 0x80000000u) ? ~u : (u | 0x80000000u);
}
__device__ __forceinline__ float fdec(unsigned k) {
    return (k & 0x80000000u) ? __uint_as_float(k ^ 0x80000000u)
                             : __uint_as_float(~k);
}

// ============================ embed ============================
__global__ void __launch_bounds__(256, 1) k_embed(
        const float* __restrict__ X, const float* __restrict__ W,
        const float* __restrict__ b, float* __restrict__ out) {
    __shared__ float s_acc[256];
    int tid = threadIdx.x;
    int row = (blockIdx.x << 2) + (tid >> 6);
    int col = tid & 63;
    const float* xr = X + (size_t)row * 128;
    float acc = 0.f;
    #pragma unroll 16
    for (int k = 0; k < 128; ++k)
        acc = fmaf(__ldg(xr + k), __ldg(W + k * 64 + col), acc);
    acc = __fadd_rn(acc, __ldg(b + col));
    out[row * 64 + col] = acc;           // X_tilde output
    g_xtT[col * NP + row] = acc;         // transposed copy for GEMM
    s_acc[tid] = acc;
    __syncthreads();
    if (tid < 128) {
        int sub = tid >> 5, lane = tid & 31;
        float a = s_acc[sub * 64 + lane];
        float c = s_acc[sub * 64 + 32 + lane];
        float v = a * a + c * c;
        #pragma unroll
        for (int o = 16; o; o >>= 1) v += __shfl_xor_sync(0xffffffffu, v, o);
        if (!lane) g_sq[(blockIdx.x << 2) + sub] = v;
    }
}

// ============================ gemm -> logits matrix ============================
struct GU {
    union {
        struct { float sA[64 * 132]; float sB[64 * 132]; } ab;
        float sC[128 * 128];
    };
    float sqi[128];
    float sqj[128];
};

__global__ void __launch_bounds__(256, 2) k_gemm(const float* __restrict__ tparam) {
    extern __shared__ char smraw[];
    GU& sm = *reinterpret_cast<GU*>(smraw);
    const int tid = threadIdx.x;

    // triangular block decode: bi <= bj
    int bidx = blockIdx.x, bi = 0;
    while (bidx >= NB - bi) { bidx -= NB - bi; ++bi; }
    const int bj = bi + bidx;
    const int I = bi * 128, J = bj * 128;
    const float scale = expf(fminf(fmaxf(tparam[0], -5.f), 5.f));
    const int ti = tid >> 4, tj = tid & 15;

    #pragma unroll
    for (int it = 0; it < 8; ++it) {
        int f = it * 256 + tid;
        int k = f >> 5, i4 = f & 31;
        *(float4*)&sm.ab.sA[k * 132 + i4 * 4] =
            *(const float4*)&g_xtT[k * NP + I + i4 * 4];
        *(float4*)&sm.ab.sB[k * 132 + i4 * 4] =
            *(const float4*)&g_xtT[k * NP + J + i4 * 4];
    }
    if (tid < 128) { sm.sqi[tid] = g_sq[I + tid]; sm.sqj[tid] = g_sq[J + tid]; }
    __syncthreads();

    float acc[8][8];
    #pragma unroll
    for (int u = 0; u < 8; ++u)
        #pragma unroll
        for (int v = 0; v < 8; ++v) acc[u][v] = 0.f;

    #pragma unroll 4
    for (int k = 0; k < 64; ++k) {
        float4 a0 = *(const float4*)&sm.ab.sA[k * 132 + ti * 4];
        float4 a1 = *(const float4*)&sm.ab.sA[k * 132 + 64 + ti * 4];
        float4 b0 = *(const float4*)&sm.ab.sB[k * 132 + tj * 4];
        float4 b1 = *(const float4*)&sm.ab.sB[k * 132 + 64 + tj * 4];
        float av[8] = {a0.x, a0.y, a0.z, a0.w, a1.x, a1.y, a1.z, a1.w};
        float bv[8] = {b0.x, b0.y, b0.z, b0.w, b1.x, b1.y, b1.z, b1.w};
        #pragma unroll
        for (int u = 0; u < 8; ++u)
            #pragma unroll
            for (int v = 0; v < 8; ++v)
                acc[u][v] = fmaf(av[u], bv[v], acc[u][v]);
    }

    // epilogue: logits in-place (exact reference op order)
    float si[8], sj[8];
    #pragma unroll
    for (int u = 0; u < 8; ++u)
        si[u] = sm.sqi[(u < 4) ? ti * 4 + u : 64 + ti * 4 + (u - 4)];
    #pragma unroll
    for (int v = 0; v < 8; ++v)
        sj[v] = sm.sqj[(v < 4) ? tj * 4 + v : 64 + tj * 4 + (v - 4)];
    #pragma unroll
    for (int u = 0; u < 8; ++u)
        #pragma unroll
        for (int v = 0; v < 8; ++v) {
            float d = __fadd_rn(__fadd_rn(si[u], sj[v]),
                                -__fmul_rn(2.0f, acc[u][v]));
            acc[u][v] = __fmul_rn(fmaxf(d, 0.0f), scale);
        }

    // direct store: block (bi rows, bj cols)
    #pragma unroll
    for (int u = 0; u < 8; ++u) {
        int gi = I + ((u < 4) ? ti * 4 + u : 64 + ti * 4 + (u - 4));
        *(float4*)&g_D[(size_t)gi * NP + J + tj * 4] =
            make_float4(acc[u][0], acc[u][1], acc[u][2], acc[u][3]);
        *(float4*)&g_D[(size_t)gi * NP + J + 64 + tj * 4] =
            make_float4(acc[u][4], acc[u][5], acc[u][6], acc[u][7]);
    }

    if (bi != bj) {
        // transposed store via swizzled smem stage (bit-identical by symmetry)
        __syncthreads();
        #pragma unroll
        for (int v = 0; v < 8; ++v) {
            int jl = (v < 4) ? tj * 4 + v : 64 + tj * 4 + (v - 4);
            int sw = ((jl >> 2) & 7) << 2;
            *(float4*)&sm.sC[jl * 128 + ((ti * 4) ^ sw)] =
                make_float4(acc[0][v], acc[1][v], acc[2][v], acc[3][v]);
            *(float4*)&sm.sC[jl * 128 + (64 + ((ti * 4) ^ sw))] =
                make_float4(acc[4][v], acc[5][v], acc[6][v], acc[7][v]);
        }
        __syncthreads();
        #pragma unroll
        for (int it = 0; it < 16; ++it) {
            int f = it * 256 + tid;
            int jl = f >> 5, i4 = f & 31;
            int sw = ((jl >> 2) & 7) << 2;
            int off = i4 * 4;
            int phys = (off < 64) ? (off ^ sw) : (64 + ((off - 64) ^ sw));
            float4 vv = *(const float4*)&sm.sC[jl * 128 + phys];
            *(float4*)&g_D[(size_t)(J + jl) * NP + I + i4 * 4] = vv;
        }
    }
}

// ============================ select: warp-per-row exact top-16 ============================
// 2048 CTAs x 128 thr = 8192 warps, one row per warp; 1-ahead pipelined D loads.
__global__ void __launch_bounds__(128) k_select(
        const float* __restrict__ q, float* __restrict__ out) {
    const int lane = threadIdx.x & 31;
    const int row = blockIdx.x * 4 + (threadIdx.x >> 5);
    const unsigned FULL = 0xffffffffu;

    const float* Drow = g_D + (size_t)row * NP;
    const float* qrow = q + (size_t)row * NP;
    // distributed sorted list: slot `lane` (lanes 0..15 are the answer)
    unsigned kHi = 0xFF800000u, kLo = 0xFFFFFFFFu;  // +inf sentinel
    float lgS = 0.f;
    float th = __int_as_float(0x7f800000);

    float4 v = *(const float4*)&Drow[lane * 4];
    for (int m = 0; m < 64; ++m) {
        // issue next load before processing current (1-ahead pipeline)
        float4 vn;
        if (m < 63) vn = *(const float4*)&Drow[((m + 1) * 32 + lane) * 4];

        bool p0 = (v.x - 17.0f) <= th;   // gumbel in [-2.92,16.64] -> exact bound
        bool p1 = (v.y - 17.0f) <= th;
        bool p2 = (v.z - 17.0f) <= th;
        bool p3 = (v.w - 17.0f) <= th;
        unsigned any = __ballot_sync(FULL, p0 | p1 | p2 | p3);
        if (any) {
            float pe0 = 0.f, pe1 = 0.f, pe2 = 0.f, pe3 = 0.f;
            if (p0 | p1 | p2 | p3) {
                float4 qv = *(const float4*)&qrow[(m * 32 + lane) * 4];
                if (p0) pe0 = __fadd_rn(v.x, logf(-logf(qv.x)));
                if (p1) pe1 = __fadd_rn(v.y, logf(-logf(qv.y)));
                if (p2) pe2 = __fadd_rn(v.z, logf(-logf(qv.z)));
                if (p3) pe3 = __fadd_rn(v.w, logf(-logf(qv.w)));
            }
            #pragma unroll
            for (int c = 0; c < 4; ++c) {
                float pc = (c == 0) ? pe0 : (c == 1) ? pe1 : (c == 2) ? pe2 : pe3;
                float vc = (c == 0) ? v.x : (c == 1) ? v.y : (c == 2) ? v.z : v.w;
                bool  pp = (c == 0) ? p0 : (c == 1) ? p1 : (c == 2) ? p2 : p3;
                unsigned mc = __ballot_sync(FULL, pp);
                while (mc) {
                    int L = __ffs(mc) - 1; mc &= mc - 1;
                    float np = __shfl_sync(FULL, pc, L);
                    float nl = __shfl_sync(FULL, vc, L);
                    unsigned nk = fenc(np);
                    unsigned nj = (unsigned)((m * 32 + L) * 4 + c);
                    bool le = (kHi < nk) | ((kHi == nk) & (kLo <= nj));
                    int pos = __popc(__ballot_sync(FULL, le));
                    unsigned sHi = __shfl_up_sync(FULL, kHi, 1);
                    unsigned sLo = __shfl_up_sync(FULL, kLo, 1);
                    float    sLg = __shfl_up_sync(FULL, lgS, 1);
                    if (lane == pos)      { kHi = nk;  kLo = nj;  lgS = nl;  }
                    else if (lane > pos)  { kHi = sHi; kLo = sLo; lgS = sLg; }
                }
            }
            th = fdec(__shfl_sync(FULL, kHi, 15));
        }
        v = vn;
    }

    if (lane < 16) {
        out[524288 + row * 16 + lane] = (float)kLo;     // edge_index[0]
        out[655360 + row * 16 + lane] = (float)row;     // edge_index[1]
        out[786432 + row * 16 + lane] = -lgS;           // logprobs
    }
}

extern "C" void kernel_launch(void* const* d_in, const int* in_sizes, int n_in,
                              void* d_out, int out_size) {
    const float* X = (const float*)d_in[0];
    const float* W = (const float*)d_in[1];
    const float* b = (const float*)d_in[2];
    const float* t = (const float*)d_in[3];
    const float* q = (const float*)d_in[4];
    float* out = (float*)d_out;

    k_embed<<<2048, 256>>>(X, W, b, out);
    int smem = (int)sizeof(GU);
    cudaFuncSetAttribute(k_gemm, cudaFuncAttributeMaxDynamicSharedMemorySize, smem);
    k_gemm<<<NB * (NB + 1) / 2, 256, smem>>>(t);
    k_select<<<2048, 128>>>(q, out);
}